// round 13
// baseline (speedup 1.0000x reference)
#include <cuda_runtime.h>
#include <math.h>

#define A_MAX    442368
#define NKEEP    1000
#define CAND_CAP 2048
#define HIST_N   1024
#define SCAN_STRIDE 33          // 32 data words + 1 pad -> conflict-free propagate loads
#define NB       148            // persistent grid: 1 block/SM, all resident (GB300 has 152 SMs)
#define TAIL_SMEM (1024 * SCAN_STRIDE * 4)   // 135168 B

// ---------------- scratch (device globals; no allocation allowed) ----------------
__device__ unsigned            g_key[A_MAX];
__device__ int                 g_argmax[A_MAX];
__device__ unsigned            g_hist4k[HIST_N];   // MUST be zero at kernel_launch entry (re-zeroed in k_tail)
__device__ unsigned            g_cnt;              // ditto
__device__ unsigned long long  g_cand[CAND_CAP];
__device__ float4              g_box[NKEEP];
__device__ float               g_area[NKEEP];
__device__ float               g_cscore[NKEEP];
__device__ int                 g_ccls[NKEEP];
__device__ unsigned            g_sup[NKEEP * 32];
__device__ volatile unsigned   g_bar_gen;
__device__ unsigned            g_bar_cnt;

__device__ __forceinline__ unsigned warp_max_u32(unsigned v) {
    unsigned r;
    asm("redux.sync.max.u32 %0, %1, 0xffffffff;" : "=r"(r) : "r"(v));
    return r;
}
__device__ __forceinline__ unsigned warp_min_u32(unsigned v) {
    unsigned r;
    asm("redux.sync.min.u32 %0, %1, 0xffffffff;" : "=r"(r) : "r"(v));
    return r;
}

// sense-reversing grid barrier; requires all NB blocks resident
__device__ __forceinline__ void grid_barrier() {
    __syncthreads();
    if (threadIdx.x == 0) {
        __threadfence();                       // release prior writes
        unsigned gen = g_bar_gen;
        if (atomicAdd(&g_bar_cnt, 1u) == NB - 1) {
            g_bar_cnt = 0;
            __threadfence();
            g_bar_gen = gen + 1;
        } else {
            while (g_bar_gen == gen) __nanosleep(64);
            __threadfence();                   // acquire
        }
    }
    __syncthreads();
}

// ---------------- stage 1: warp-per-anchor max/argmax (integer redux on bits) ----------------
__global__ void __launch_bounds__(256) k_reduce(const float* __restrict__ cla, int A) {
    __shared__ unsigned hist[HIST_N];
    for (int b = threadIdx.x; b < HIST_N; b += 256) hist[b] = 0;
    __syncthreads();

    int lane = threadIdx.x & 31;
    int gw   = blockIdx.x * 8 + (threadIdx.x >> 5);
    int nw   = gridDim.x * 8;

    for (int a = gw; a < A; a += 2 * nw) {
        int a2 = a + nw;
        bool h2 = a2 < A;
        const float* p  = cla + (size_t)a * 80;
        const float* p2 = cla + (size_t)(h2 ? a2 : a) * 80;

        // scores are uniform[0,1) -> non-negative -> bit pattern monotone
        float f0a = p[lane],  f1a = p[32 + lane];
        float f2a = (lane < 16) ? p[64 + lane] : 0.0f;
        float f0b = p2[lane], f1b = p2[32 + lane];
        float f2b = (lane < 16) ? p2[64 + lane] : 0.0f;

        float va = f0a; int ixa = lane;
        if (f1a > va) { va = f1a; ixa = lane + 32; }
        if (f2a > va) { va = f2a; ixa = lane + 64; }
        float vb = f0b; int ixb = lane;
        if (f1b > vb) { vb = f1b; ixb = lane + 32; }
        if (f2b > vb) { vb = f2b; ixb = lane + 64; }

        unsigned mba = warp_max_u32(__float_as_uint(va));
        unsigned mbb = warp_max_u32(__float_as_uint(vb));
        float mva = __uint_as_float(mba);
        float mvb = __uint_as_float(mbb);
        unsigned cia = (__float_as_uint(va) == mba) ? (unsigned)ixa : 0xFFFFu;
        unsigned cib = (__float_as_uint(vb) == mbb) ? (unsigned)ixb : 0xFFFFu;
        unsigned mia = warp_min_u32(cia);
        unsigned mib = warp_min_u32(cib);

        if (lane == 0) {
            float ma = fmaxf(1.0f - mva, 0.0f);
            unsigned ua = __float_as_uint(ma);
            g_key[a] = ua; g_argmax[a] = (int)mia;
            atomicAdd(&hist[min(ua >> 20, (unsigned)(HIST_N - 1))], 1u);
            if (h2) {
                float mb = fmaxf(1.0f - mvb, 0.0f);
                unsigned ub = __float_as_uint(mb);
                g_key[a2] = ub; g_argmax[a2] = (int)mib;
                atomicAdd(&hist[min(ub >> 20, (unsigned)(HIST_N - 1))], 1u);
            }
        }
    }
    __syncthreads();
    for (int b = threadIdx.x; b < HIST_N; b += 256) {
        unsigned s = hist[b];
        if (s) atomicAdd(&g_hist4k[b], s);
    }
}

// ---------------- fused tail: compact -> rank/decode -> iou -> scan -> output ----------------
__global__ void __launch_bounds__(256) k_tail(const float4* __restrict__ anchors,
                                              const float4* __restrict__ reg,
                                              float* __restrict__ out, int A4) {
    extern __shared__ unsigned smem_raw[];
    __shared__ unsigned scn[256];
    __shared__ unsigned sB;
    __shared__ unsigned sn;
    __shared__ unsigned svalid[32];
    __shared__ unsigned skeep[32];

    int t   = threadIdx.x;
    int bid = blockIdx.x;

    // ===== Phase A: threshold-bin select + compact =====
    {
        uint4 h = ((const uint4*)g_hist4k)[t];
        unsigned ls = h.x + h.y + h.z + h.w;
        scn[t] = ls;
        __syncthreads();
        for (int off = 1; off < 256; off <<= 1) {
            unsigned v = (t >= off) ? scn[t - off] : 0u;
            __syncthreads();
            scn[t] += v;
            __syncthreads();
        }
        unsigned cum  = scn[t];
        unsigned prev = cum - ls;
        if (prev < NKEEP && cum >= NKEEP) {
            unsigned r = prev, B;
            if      (r + h.x >= NKEEP) B = 4 * t;
            else if (r + h.x + h.y >= NKEEP) B = 4 * t + 1;
            else if (r + h.x + h.y + h.z >= NKEEP) B = 4 * t + 2;
            else B = 4 * t + 3;
            sB = B;
        }
        __syncthreads();
        unsigned B = sB;

        for (int i = bid * 256 + t; i < A4; i += NB * 256) {
            uint4 k4 = ((const uint4*)g_key)[i];
            unsigned base = 4u * (unsigned)i;
            if ((k4.x >> 20) <= B) { unsigned s = atomicAdd(&g_cnt, 1u); if (s < CAND_CAP) g_cand[s] = (((unsigned long long)k4.x) << 32) | base; }
            if ((k4.y >> 20) <= B) { unsigned s = atomicAdd(&g_cnt, 1u); if (s < CAND_CAP) g_cand[s] = (((unsigned long long)k4.y) << 32) | (base + 1); }
            if ((k4.z >> 20) <= B) { unsigned s = atomicAdd(&g_cnt, 1u); if (s < CAND_CAP) g_cand[s] = (((unsigned long long)k4.z) << 32) | (base + 2); }
            if ((k4.w >> 20) <= B) { unsigned s = atomicAdd(&g_cnt, 1u); if (s < CAND_CAP) g_cand[s] = (((unsigned long long)k4.w) << 32) | (base + 3); }
        }
    }
    grid_barrier();

    // ===== Phase B: rank-by-counting (blocks 0..127, 16 threads/slot) + decode/clip =====
    if (bid < 128) {
        unsigned long long* s = (unsigned long long*)smem_raw;   // 16 KB
        if (t == 0) { unsigned c = g_cnt; sn = (c > CAND_CAP) ? CAND_CAP : c; }
        __syncthreads();
        unsigned n = sn;
        for (int i = t; i < (int)n; i += 256) s[i] = g_cand[i];
        __syncthreads();

        unsigned gt   = bid * 256 + t;
        unsigned slot = gt >> 4;
        unsigned sub  = gt & 15;
        bool live = (slot < n);

        unsigned long long mine = live ? s[slot] : 0ull;
        unsigned r = 0;
        if (live) {
            unsigned chunk = (n + 15) >> 4;
            unsigned j0 = sub * chunk;
            unsigned j1 = j0 + chunk; if (j1 > n) j1 = n;
            for (unsigned j = j0; j < j1; j++) r += (s[j] < mine);
        }
        r += __shfl_xor_sync(0xFFFFFFFFu, r, 1);
        r += __shfl_xor_sync(0xFFFFFFFFu, r, 2);
        r += __shfl_xor_sync(0xFFFFFFFFu, r, 4);
        r += __shfl_xor_sync(0xFFFFFFFFu, r, 8);

        if (live && sub == 0 && r < NKEEP) {
            unsigned idx = (unsigned)mine;
            float m  = __uint_as_float((unsigned)(mine >> 32));
            float sc = 1.0f - m;

            float4 an = anchors[idx];
            float4 dg = reg[idx];
            float wa = an.z - an.x, ha = an.w - an.y;
            float cxa = an.x + 0.5f * wa, cya = an.y + 0.5f * ha;
            float cx = cxa + dg.x * wa, cy = cya + dg.y * ha;
            float w  = wa * expf(dg.z), hh = ha * expf(dg.w);
            float x1 = fminf(fmaxf(cx - 0.5f * w, 0.0f), 1535.0f);
            float y1 = fminf(fmaxf(cy - 0.5f * hh, 0.0f), 1535.0f);
            float x2 = fminf(fmaxf(cx + 0.5f * w, 0.0f), 1535.0f);
            float y2 = fminf(fmaxf(cy + 0.5f * hh, 0.0f), 1535.0f);

            g_box[r]    = make_float4(x1, y1, x2, y2);
            g_area[r]   = fmaxf(x2 - x1, 0.0f) * fmaxf(y2 - y1, 0.0f);
            g_cscore[r] = sc;
            g_ccls[r]   = g_argmax[idx];
        }
    }
    grid_barrier();

    // ===== Phase C: suppression mask (+ block 147 zeroes hist/cnt for next launch) =====
    if (bid == NB - 1) {
        for (int b = t; b < HIST_N; b += 256) g_hist4k[b] = 0;
        if (t == 0) g_cnt = 0;
    } else {
        float4* sbox  = (float4*)smem_raw;                 // 16 KB
        float*  sarea = (float*)(smem_raw + 4096);         // 4 KB
        for (int i = t; i < NKEEP; i += 256) { sbox[i] = g_box[i]; sarea[i] = g_area[i]; }
        __syncthreads();

        int W    = bid * 8 + (t >> 5);      // up to 147*8+7 = 1183; tasks 0..1023
        int lane = t & 31;
        if (W < 1024) {
            int jw    = W & 31;
            int chunk = W >> 5;
            int i0   = chunk * 32;
            int iend = i0 + 32; if (iend > NKEEP) iend = NKEEP;
            int j = jw * 32 + lane;
            bool jv = (j < NKEEP);
            float jx1 = 0, jy1 = 0, jx2 = 0, jy2 = 0, ja = 0;
            if (jv) {
                float4 b = sbox[j];
                jx1 = b.x; jy1 = b.y; jx2 = b.z; jy2 = b.w;
                ja = sarea[j];
            }
            for (int i = i0; i < iend; i++) {
                float4 bi = sbox[i];
                float ai  = sarea[i];
                float iw = fminf(bi.z, jx2) - fmaxf(bi.x, jx1); iw = fmaxf(iw, 0.0f);
                float ih = fminf(bi.w, jy2) - fmaxf(bi.y, jy1); ih = fmaxf(ih, 0.0f);
                float inter = iw * ih;
                float uni   = ai + ja - inter;
                bool pred = jv && (inter / fmaxf(uni, 1e-8f) > 0.5f);
                unsigned m = __ballot_sync(0xFFFFFFFFu, pred);
                if (lane == 0) g_sup[i * 32 + jw] = m;
            }
        }
    }
    grid_barrier();

    // ===== Phase D: tile-blocked sequential NMS + output (block 0 only) =====
    if (bid != 0) return;
    {
        unsigned* ssup = smem_raw;          // 1024 x 33 words padded
        for (int idx = t; idx < 32768; idx += 256) {
            int r = idx >> 5, w = idx & 31;
            ssup[r * SCAN_STRIDE + w] = (r < NKEEP) ? g_sup[idx] : 0u;
        }
        for (int base = 0; base < 1024; base += 256) {
            int i = base + t;
            float sc = (i < NKEEP) ? g_cscore[i] : 0.0f;
            unsigned bm = __ballot_sync(0xFFFFFFFFu, sc > 0.5f);
            if ((t & 31) == 0) svalid[i >> 5] = bm;
        }
        __syncthreads();

        if (t < 32) {
            int lane = t;
            unsigned rem = 0;
            unsigned keepw = 0;
            unsigned validw = svalid[lane];
            for (int tt = 0; tt < 32; tt++) {
                unsigned rowv[32];
#pragma unroll
                for (int b = 0; b < 32; b++)
                    rowv[b] = ssup[(32 * tt + b) * SCAN_STRIDE + tt];
                unsigned W = __ballot_sync(0xFFFFFFFFu, (rem >> tt) & 1u);
                unsigned V = __shfl_sync(0xFFFFFFFFu, validw, tt);
                unsigned K = 0;
#pragma unroll
                for (int b = 0; b < 32; b++) {
                    if (((V >> b) & 1u) && !((W >> b) & 1u) && ((rowv[b] & K) == 0u))
                        K |= 1u << b;
                }
                if (lane == tt) keepw = K;
#pragma unroll
                for (int s = 1; s < 32; s++) {
                    if (s > tt) {
                        unsigned c = ssup[(32 * s + lane) * SCAN_STRIDE + tt];
                        if (c & K) rem |= 1u << s;
                    }
                }
            }
            skeep[lane] = keepw;
        }
        __syncthreads();

        for (int base = 0; base < NKEEP; base += 256) {
            int i = base + t;
            if (i < NKEEP) {
                bool kp = (skeep[i >> 5] >> (i & 31)) & 1u;
                out[i]         = kp ? g_cscore[i] : 0.0f;
                out[NKEEP + i] = kp ? (float)g_ccls[i] : -1.0f;
                float4 b = kp ? g_box[i] : make_float4(0, 0, 0, 0);
                ((float4*)(out + 2 * NKEEP))[i] = b;
            }
        }
    }
}

// ---------------- launch ----------------
extern "C" void kernel_launch(void* const* d_in, const int* in_sizes, int n_in,
                              void* d_out, int out_size) {
    const float*  cla     = (const float*)d_in[0];
    const float4* reg     = (const float4*)d_in[1];
    const float4* anchors = (const float4*)d_in[2];
    int A = in_sizes[0] / 80;
    float* out = (float*)d_out;

    cudaFuncSetAttribute(k_tail, cudaFuncAttributeMaxDynamicSharedMemorySize, TAIL_SMEM);

    k_reduce<<<1184, 256>>>(cla, A);
    k_tail<<<NB, 256, TAIL_SMEM>>>(anchors, reg, out, A / 4);
}

// round 14
// speedup vs baseline: 1.1054x; 1.1054x over previous
#include <cuda_runtime.h>
#include <math.h>

#define A_MAX    442368
#define NKEEP    1000
#define CAND_CAP 2048
#define HIST_N   1024
#define SCAN_STRIDE 33          // 32 data words + 1 pad -> conflict-free propagate loads
#define NB       148            // persistent grid: 1 block/SM, all resident
#define TAIL_SMEM (1024 * SCAN_STRIDE * 4)   // 135168 B

// ---------------- scratch (device globals; no allocation allowed) ----------------
__device__ unsigned            g_key[A_MAX];
__device__ int                 g_argmax[A_MAX];
__device__ unsigned            g_hist4k[HIST_N];   // zero at entry (re-zeroed in k_tail)
__device__ unsigned            g_cnt;              // ditto
__device__ unsigned long long  g_cand[CAND_CAP];
__device__ float4              g_box[NKEEP];
__device__ float               g_area[NKEEP];
__device__ float               g_cscore[NKEEP];
__device__ int                 g_ccls[NKEEP];
__device__ unsigned            g_sup[NKEEP * 32];
__device__ volatile unsigned   g_bar_gen;
__device__ unsigned            g_bar_cnt;

__device__ __forceinline__ unsigned warp_max_u32(unsigned v) {
    unsigned r;
    asm("redux.sync.max.u32 %0, %1, 0xffffffff;" : "=r"(r) : "r"(v));
    return r;
}
__device__ __forceinline__ unsigned warp_min_u32(unsigned v) {
    unsigned r;
    asm("redux.sync.min.u32 %0, %1, 0xffffffff;" : "=r"(r) : "r"(v));
    return r;
}

// sense-reversing grid barrier; requires all NB blocks resident
__device__ __forceinline__ void grid_barrier() {
    __syncthreads();
    if (threadIdx.x == 0) {
        __threadfence();
        unsigned gen = g_bar_gen;
        if (atomicAdd(&g_bar_cnt, 1u) == NB - 1) {
            g_bar_cnt = 0;
            __threadfence();
            g_bar_gen = gen + 1;
        } else {
            while (g_bar_gen == gen) __nanosleep(64);
            __threadfence();
        }
    }
    __syncthreads();
}

// ---------------- stage 1: warp-per-anchor max/argmax (integer redux on bits) ----------------
__global__ void __launch_bounds__(256) k_reduce(const float* __restrict__ cla, int A) {
    __shared__ unsigned hist[HIST_N];
    for (int b = threadIdx.x; b < HIST_N; b += 256) hist[b] = 0;
    __syncthreads();

    int lane = threadIdx.x & 31;
    int gw   = blockIdx.x * 8 + (threadIdx.x >> 5);
    int nw   = gridDim.x * 8;

    for (int a = gw; a < A; a += 2 * nw) {
        int a2 = a + nw;
        bool h2 = a2 < A;
        const float* p  = cla + (size_t)a * 80;
        const float* p2 = cla + (size_t)(h2 ? a2 : a) * 80;

        // streaming loads: cla is touched once -> evict-first keeps L2 for the tail
        float f0a = __ldcs(p + lane),  f1a = __ldcs(p + 32 + lane);
        float f2a = (lane < 16) ? __ldcs(p + 64 + lane) : 0.0f;
        float f0b = __ldcs(p2 + lane), f1b = __ldcs(p2 + 32 + lane);
        float f2b = (lane < 16) ? __ldcs(p2 + 64 + lane) : 0.0f;

        float va = f0a; int ixa = lane;
        if (f1a > va) { va = f1a; ixa = lane + 32; }
        if (f2a > va) { va = f2a; ixa = lane + 64; }
        float vb = f0b; int ixb = lane;
        if (f1b > vb) { vb = f1b; ixb = lane + 32; }
        if (f2b > vb) { vb = f2b; ixb = lane + 64; }

        unsigned mba = warp_max_u32(__float_as_uint(va));
        unsigned mbb = warp_max_u32(__float_as_uint(vb));
        float mva = __uint_as_float(mba);
        float mvb = __uint_as_float(mbb);
        unsigned cia = (__float_as_uint(va) == mba) ? (unsigned)ixa : 0xFFFFu;
        unsigned cib = (__float_as_uint(vb) == mbb) ? (unsigned)ixb : 0xFFFFu;
        unsigned mia = warp_min_u32(cia);
        unsigned mib = warp_min_u32(cib);

        if (lane == 0) {
            float ma = fmaxf(1.0f - mva, 0.0f);
            unsigned ua = __float_as_uint(ma);
            g_key[a] = ua; g_argmax[a] = (int)mia;
            atomicAdd(&hist[min(ua >> 20, (unsigned)(HIST_N - 1))], 1u);
            if (h2) {
                float mb = fmaxf(1.0f - mvb, 0.0f);
                unsigned ub = __float_as_uint(mb);
                g_key[a2] = ub; g_argmax[a2] = (int)mib;
                atomicAdd(&hist[min(ub >> 20, (unsigned)(HIST_N - 1))], 1u);
            }
        }
    }
    __syncthreads();
    for (int b = threadIdx.x; b < HIST_N; b += 256) {
        unsigned s = hist[b];
        if (s) atomicAdd(&g_hist4k[b], s);
    }
}

// ---------------- fused tail: compact -> rank/decode -> iou -> scan -> output ----------------
__global__ void __launch_bounds__(256) k_tail(const float4* __restrict__ anchors,
                                              const float4* __restrict__ reg,
                                              float* __restrict__ out, int A4) {
    extern __shared__ unsigned smem_raw[];
    __shared__ unsigned scn[256];
    __shared__ unsigned sB;
    __shared__ unsigned sn;
    __shared__ unsigned svalid[32];
    __shared__ unsigned skeep[32];

    int t   = threadIdx.x;
    int bid = blockIdx.x;

    // ===== Phase A: threshold-bin select + compact =====
    {
        uint4 h = ((const uint4*)g_hist4k)[t];
        unsigned ls = h.x + h.y + h.z + h.w;
        scn[t] = ls;
        __syncthreads();
        for (int off = 1; off < 256; off <<= 1) {
            unsigned v = (t >= off) ? scn[t - off] : 0u;
            __syncthreads();
            scn[t] += v;
            __syncthreads();
        }
        unsigned cum  = scn[t];
        unsigned prev = cum - ls;
        if (prev < NKEEP && cum >= NKEEP) {
            unsigned r = prev, B;
            if      (r + h.x >= NKEEP) B = 4 * t;
            else if (r + h.x + h.y >= NKEEP) B = 4 * t + 1;
            else if (r + h.x + h.y + h.z >= NKEEP) B = 4 * t + 2;
            else B = 4 * t + 3;
            sB = B;
        }
        __syncthreads();
        unsigned B = sB;

        for (int i = bid * 256 + t; i < A4; i += NB * 256) {
            uint4 k4 = ((const uint4*)g_key)[i];
            unsigned base = 4u * (unsigned)i;
            if ((k4.x >> 20) <= B) { unsigned s = atomicAdd(&g_cnt, 1u); if (s < CAND_CAP) g_cand[s] = (((unsigned long long)k4.x) << 32) | base; }
            if ((k4.y >> 20) <= B) { unsigned s = atomicAdd(&g_cnt, 1u); if (s < CAND_CAP) g_cand[s] = (((unsigned long long)k4.y) << 32) | (base + 1); }
            if ((k4.z >> 20) <= B) { unsigned s = atomicAdd(&g_cnt, 1u); if (s < CAND_CAP) g_cand[s] = (((unsigned long long)k4.z) << 32) | (base + 2); }
            if ((k4.w >> 20) <= B) { unsigned s = atomicAdd(&g_cnt, 1u); if (s < CAND_CAP) g_cand[s] = (((unsigned long long)k4.w) << 32) | (base + 3); }
        }
    }
    grid_barrier();

    // ===== Phase B: rank-by-counting (blocks 0..127) + decode/clip =====
    // sub-lanes walk j = sub, sub+16, sub+32, ... : 16 consecutive u64 per warp-half
    // per access -> conflict-free LDS (the contiguous-chunk version was 16-way conflicted)
    if (bid < 128) {
        unsigned long long* s = (unsigned long long*)smem_raw;   // 16 KB
        if (t == 0) { unsigned c = g_cnt; sn = (c > CAND_CAP) ? CAND_CAP : c; }
        __syncthreads();
        unsigned n = sn;
        for (int i = t; i < (int)n; i += 256) s[i] = g_cand[i];
        __syncthreads();

        unsigned gt   = bid * 256 + t;
        unsigned slot = gt >> 4;
        unsigned sub  = gt & 15;
        bool live = (slot < n);

        unsigned long long mine = live ? s[slot] : 0ull;
        unsigned r = 0;
        if (live) {
            for (unsigned j = sub; j < n; j += 16) r += (s[j] < mine);
        }
        r += __shfl_xor_sync(0xFFFFFFFFu, r, 1);
        r += __shfl_xor_sync(0xFFFFFFFFu, r, 2);
        r += __shfl_xor_sync(0xFFFFFFFFu, r, 4);
        r += __shfl_xor_sync(0xFFFFFFFFu, r, 8);

        if (live && sub == 0 && r < NKEEP) {
            unsigned idx = (unsigned)mine;
            float m  = __uint_as_float((unsigned)(mine >> 32));
            float sc = 1.0f - m;

            float4 an = anchors[idx];
            float4 dg = reg[idx];
            float wa = an.z - an.x, ha = an.w - an.y;
            float cxa = an.x + 0.5f * wa, cya = an.y + 0.5f * ha;
            float cx = cxa + dg.x * wa, cy = cya + dg.y * ha;
            float w  = wa * expf(dg.z), hh = ha * expf(dg.w);
            float x1 = fminf(fmaxf(cx - 0.5f * w, 0.0f), 1535.0f);
            float y1 = fminf(fmaxf(cy - 0.5f * hh, 0.0f), 1535.0f);
            float x2 = fminf(fmaxf(cx + 0.5f * w, 0.0f), 1535.0f);
            float y2 = fminf(fmaxf(cy + 0.5f * hh, 0.0f), 1535.0f);

            g_box[r]    = make_float4(x1, y1, x2, y2);
            g_area[r]   = fmaxf(x2 - x1, 0.0f) * fmaxf(y2 - y1, 0.0f);
            g_cscore[r] = sc;
            g_ccls[r]   = g_argmax[idx];
        }
    }
    grid_barrier();

    // ===== Phase C: suppression mask (+ block 147 zeroes hist/cnt for next launch) =====
    if (bid == NB - 1) {
        for (int b = t; b < HIST_N; b += 256) g_hist4k[b] = 0;
        if (t == 0) g_cnt = 0;
    } else {
        float4* sbox  = (float4*)smem_raw;                 // 16 KB
        float*  sarea = (float*)(smem_raw + 4096);         // 4 KB
        for (int i = t; i < NKEEP; i += 256) { sbox[i] = g_box[i]; sarea[i] = g_area[i]; }
        __syncthreads();

        int W    = bid * 8 + (t >> 5);
        int lane = t & 31;
        if (W < 1024) {
            int jw    = W & 31;
            int chunk = W >> 5;
            int i0   = chunk * 32;
            int iend = i0 + 32; if (iend > NKEEP) iend = NKEEP;
            int j = jw * 32 + lane;
            bool jv = (j < NKEEP);
            float jx1 = 0, jy1 = 0, jx2 = 0, jy2 = 0, ja = 0;
            if (jv) {
                float4 b = sbox[j];
                jx1 = b.x; jy1 = b.y; jx2 = b.z; jy2 = b.w;
                ja = sarea[j];
            }
            for (int i = i0; i < iend; i++) {
                float4 bi = sbox[i];
                float ai  = sarea[i];
                float iw = fminf(bi.z, jx2) - fmaxf(bi.x, jx1); iw = fmaxf(iw, 0.0f);
                float ih = fminf(bi.w, jy2) - fmaxf(bi.y, jy1); ih = fmaxf(ih, 0.0f);
                float inter = iw * ih;
                float uni   = ai + ja - inter;
                bool pred = jv && (inter / fmaxf(uni, 1e-8f) > 0.5f);
                unsigned m = __ballot_sync(0xFFFFFFFFu, pred);
                if (lane == 0) g_sup[i * 32 + jw] = m;
            }
        }
    }
    grid_barrier();

    // ===== Phase D: tile-blocked sequential NMS + output (block 0 only) =====
    if (bid != 0) return;
    {
        unsigned* ssup = smem_raw;          // 1024 x 33 words padded
        for (int idx = t; idx < 32768; idx += 256) {
            int r = idx >> 5, w = idx & 31;
            ssup[r * SCAN_STRIDE + w] = (r < NKEEP) ? g_sup[idx] : 0u;
        }
        for (int base = 0; base < 1024; base += 256) {
            int i = base + t;
            float sc = (i < NKEEP) ? g_cscore[i] : 0.0f;
            unsigned bm = __ballot_sync(0xFFFFFFFFu, sc > 0.5f);
            if ((t & 31) == 0) svalid[i >> 5] = bm;
        }
        __syncthreads();

        if (t < 32) {
            int lane = t;
            unsigned rem = 0;
            unsigned keepw = 0;
            unsigned validw = svalid[lane];
            for (int tt = 0; tt < 32; tt++) {
                unsigned rowv[32];
#pragma unroll
                for (int b = 0; b < 32; b++)
                    rowv[b] = ssup[(32 * tt + b) * SCAN_STRIDE + tt];
                unsigned W = __ballot_sync(0xFFFFFFFFu, (rem >> tt) & 1u);
                unsigned V = __shfl_sync(0xFFFFFFFFu, validw, tt);
                unsigned K = 0;
#pragma unroll
                for (int b = 0; b < 32; b++) {
                    if (((V >> b) & 1u) && !((W >> b) & 1u) && ((rowv[b] & K) == 0u))
                        K |= 1u << b;
                }
                if (lane == tt) keepw = K;
#pragma unroll
                for (int s = 1; s < 32; s++) {
                    if (s > tt) {
                        unsigned c = ssup[(32 * s + lane) * SCAN_STRIDE + tt];
                        if (c & K) rem |= 1u << s;
                    }
                }
            }
            skeep[lane] = keepw;
        }
        __syncthreads();

        for (int base = 0; base < NKEEP; base += 256) {
            int i = base + t;
            if (i < NKEEP) {
                bool kp = (skeep[i >> 5] >> (i & 31)) & 1u;
                out[i]         = kp ? g_cscore[i] : 0.0f;
                out[NKEEP + i] = kp ? (float)g_ccls[i] : -1.0f;
                float4 b = kp ? g_box[i] : make_float4(0, 0, 0, 0);
                ((float4*)(out + 2 * NKEEP))[i] = b;
            }
        }
    }
}

// ---------------- launch ----------------
extern "C" void kernel_launch(void* const* d_in, const int* in_sizes, int n_in,
                              void* d_out, int out_size) {
    const float*  cla     = (const float*)d_in[0];
    const float4* reg     = (const float4*)d_in[1];
    const float4* anchors = (const float4*)d_in[2];
    int A = in_sizes[0] / 80;
    float* out = (float*)d_out;

    cudaFuncSetAttribute(k_tail, cudaFuncAttributeMaxDynamicSharedMemorySize, TAIL_SMEM);

    k_reduce<<<1184, 256>>>(cla, A);
    k_tail<<<NB, 256, TAIL_SMEM>>>(anchors, reg, out, A / 4);
}

// round 17
// speedup vs baseline: 1.1935x; 1.0797x over previous
#include <cuda_runtime.h>
#include <math.h>

#define A_MAX    442368
#define NKEEP    1000
#define CAND_CAP 2048
#define HIST_N   1024
#define SCAN_STRIDE 33          // 32 data words + 1 pad -> conflict-free propagate loads
#define SCAN_SMEM (1024 * SCAN_STRIDE * 4)   // 135168 B

// ---------------- scratch (device globals; no allocation allowed) ----------------
__device__ unsigned            g_key[A_MAX];
__device__ unsigned            g_hist4k[HIST_N];   // zero at entry (re-zeroed in k_iou blk 128)
__device__ unsigned            g_cnt;              // ditto
__device__ unsigned long long  g_cand[CAND_CAP];
__device__ float4              g_box[NKEEP];
__device__ float               g_area[NKEEP];
__device__ float               g_cscore[NKEEP];
__device__ int                 g_ccls[NKEEP];
__device__ unsigned            g_sup[NKEEP * 32];

__device__ __forceinline__ unsigned warp_max_u32(unsigned v) {
    unsigned r;
    asm("redux.sync.max.u32 %0, %1, 0xffffffff;" : "=r"(r) : "r"(v));
    return r;
}

// ---------------- stage 1: warp-per-anchor bit-max (no argmax) + fused hist ----------------
__global__ void __launch_bounds__(256) k_reduce(const float* __restrict__ cla, int A) {
    __shared__ unsigned hist[HIST_N];
    for (int b = threadIdx.x; b < HIST_N; b += 256) hist[b] = 0;
    __syncthreads();

    int lane = threadIdx.x & 31;
    int gw   = blockIdx.x * 8 + (threadIdx.x >> 5);
    int nw   = gridDim.x * 8;

    for (int a = gw; a < A; a += 2 * nw) {
        int a2 = a + nw;
        bool h2 = a2 < A;
        const float* p  = cla + (size_t)a * 80;
        const float* p2 = cla + (size_t)(h2 ? a2 : a) * 80;

        // scores uniform[0,1) -> non-negative -> bit pattern monotone; streamed (read once)
        float f0a = __ldcs(p + lane),  f1a = __ldcs(p + 32 + lane);
        float f2a = (lane < 16) ? __ldcs(p + 64 + lane) : 0.0f;
        float f0b = __ldcs(p2 + lane), f1b = __ldcs(p2 + 32 + lane);
        float f2b = (lane < 16) ? __ldcs(p2 + 64 + lane) : 0.0f;

        float va = fmaxf(fmaxf(f0a, f1a), f2a);
        float vb = fmaxf(fmaxf(f0b, f1b), f2b);

        unsigned mba = warp_max_u32(__float_as_uint(va));
        unsigned mbb = warp_max_u32(__float_as_uint(vb));

        if (lane == 0) {
            float ma = fmaxf(1.0f - __uint_as_float(mba), 0.0f);
            unsigned ua = __float_as_uint(ma);
            g_key[a] = ua;
            atomicAdd(&hist[ua >> 20], 1u);
            if (h2) {
                float mb = fmaxf(1.0f - __uint_as_float(mbb), 0.0f);
                unsigned ub = __float_as_uint(mb);
                g_key[a2] = ub;
                atomicAdd(&hist[ub >> 20], 1u);
            }
        }
    }
    __syncthreads();
    for (int b = threadIdx.x; b < HIST_N; b += 256) {
        unsigned s = hist[b];
        if (s) atomicAdd(&g_hist4k[b], s);
    }
}

// ---------------- stage 2: threshold-bin select + compact ----------------
__global__ void __launch_bounds__(256) k_compact(int A4) {
    __shared__ unsigned scn[256];
    __shared__ unsigned sB;
    int t = threadIdx.x;

    uint4 h = ((const uint4*)g_hist4k)[t];
    unsigned ls = h.x + h.y + h.z + h.w;
    scn[t] = ls;
    __syncthreads();
    for (int off = 1; off < 256; off <<= 1) {
        unsigned v = (t >= off) ? scn[t - off] : 0u;
        __syncthreads();
        scn[t] += v;
        __syncthreads();
    }
    unsigned cum  = scn[t];
    unsigned prev = cum - ls;
    if (prev < NKEEP && cum >= NKEEP) {
        unsigned r = prev, B;
        if      (r + h.x >= NKEEP) B = 4 * t;
        else if (r + h.x + h.y >= NKEEP) B = 4 * t + 1;
        else if (r + h.x + h.y + h.z >= NKEEP) B = 4 * t + 2;
        else B = 4 * t + 3;
        sB = B;
    }
    __syncthreads();
    unsigned B = sB;

    for (int i = blockIdx.x * 256 + t; i < A4; i += gridDim.x * 256) {
        uint4 k4 = ((const uint4*)g_key)[i];
        unsigned base = 4u * (unsigned)i;
        if ((k4.x >> 20) <= B) { unsigned s = atomicAdd(&g_cnt, 1u); if (s < CAND_CAP) g_cand[s] = (((unsigned long long)k4.x) << 32) | base; }
        if ((k4.y >> 20) <= B) { unsigned s = atomicAdd(&g_cnt, 1u); if (s < CAND_CAP) g_cand[s] = (((unsigned long long)k4.y) << 32) | (base + 1); }
        if ((k4.z >> 20) <= B) { unsigned s = atomicAdd(&g_cnt, 1u); if (s < CAND_CAP) g_cand[s] = (((unsigned long long)k4.z) << 32) | (base + 2); }
        if ((k4.w >> 20) <= B) { unsigned s = atomicAdd(&g_cnt, 1u); if (s < CAND_CAP) g_cand[s] = (((unsigned long long)k4.w) << 32) | (base + 3); }
    }
}

// ---------------- stage 3: rank-by-counting + decode/clip + argmax recompute ----------------
__global__ void __launch_bounds__(256) k_rank(const float4* __restrict__ anchors,
                                              const float4* __restrict__ reg,
                                              const float* __restrict__ cla) {
    __shared__ unsigned long long s[CAND_CAP];
    __shared__ unsigned sn;
    int t = threadIdx.x;
    if (t == 0) { unsigned c = g_cnt; sn = (c > CAND_CAP) ? CAND_CAP : c; }
    __syncthreads();
    unsigned n = sn;
    for (int i = t; i < (int)n; i += 256) s[i] = g_cand[i];
    __syncthreads();

    unsigned gt   = blockIdx.x * 256 + t;
    unsigned slot = gt >> 4;
    unsigned sub  = gt & 15;
    bool live = (slot < n);

    unsigned long long mine = live ? s[slot] : 0ull;
    unsigned r = 0;
    if (live) {
        // stride-16 interleaved walk: 16 sub-lanes hit 16 consecutive u64 -> conflict-free
        for (unsigned j = sub; j < n; j += 16) r += (s[j] < mine);
    }
    r += __shfl_xor_sync(0xFFFFFFFFu, r, 1);
    r += __shfl_xor_sync(0xFFFFFFFFu, r, 2);
    r += __shfl_xor_sync(0xFFFFFFFFu, r, 4);
    r += __shfl_xor_sync(0xFFFFFFFFu, r, 8);

    if (live && sub == 0 && r < NKEEP) {
        unsigned idx = (unsigned)mine;
        float m  = __uint_as_float((unsigned)(mine >> 32));
        float sc = 1.0f - m;

        // argmax recompute (first occurrence of max == jnp.argmax semantics)
        const float4* row = (const float4*)(cla + (size_t)idx * 80);
        float best = -1.0f; int bi = 0;
#pragma unroll
        for (int q = 0; q < 20; q++) {
            float4 v = row[q];
            if (v.x > best) { best = v.x; bi = 4*q;   }
            if (v.y > best) { best = v.y; bi = 4*q+1; }
            if (v.z > best) { best = v.z; bi = 4*q+2; }
            if (v.w > best) { best = v.w; bi = 4*q+3; }
        }

        float4 an = anchors[idx];
        float4 dg = reg[idx];
        float wa = an.z - an.x, ha = an.w - an.y;
        float cxa = an.x + 0.5f * wa, cya = an.y + 0.5f * ha;
        float cx = cxa + dg.x * wa, cy = cya + dg.y * ha;
        float w  = wa * expf(dg.z), hh = ha * expf(dg.w);
        float x1 = fminf(fmaxf(cx - 0.5f * w, 0.0f), 1535.0f);
        float y1 = fminf(fmaxf(cy - 0.5f * hh, 0.0f), 1535.0f);
        float x2 = fminf(fmaxf(cx + 0.5f * w, 0.0f), 1535.0f);
        float y2 = fminf(fmaxf(cy + 0.5f * hh, 0.0f), 1535.0f);

        g_box[r]    = make_float4(x1, y1, x2, y2);
        g_area[r]   = fmaxf(x2 - x1, 0.0f) * fmaxf(y2 - y1, 0.0f);
        g_cscore[r] = sc;
        g_ccls[r]   = bi;
    }
}

// ---------------- stage 4: suppression mask (block 128 = scratch cleanup) ----------------
__global__ void __launch_bounds__(256) k_iou() {
    int t = threadIdx.x;
    if (blockIdx.x == 128) {
        for (int b = t; b < HIST_N; b += 256) g_hist4k[b] = 0;
        if (t == 0) g_cnt = 0;
        return;
    }
    __shared__ float4 sbox[NKEEP];
    __shared__ float  sarea[NKEEP];
    for (int i = t; i < NKEEP; i += 256) { sbox[i] = g_box[i]; sarea[i] = g_area[i]; }
    __syncthreads();

    int W    = blockIdx.x * 8 + (t >> 5);   // 0..1023
    int lane = t & 31;
    int jw    = W & 31;
    int chunk = W >> 5;
    int i0   = chunk * 32;
    int iend = i0 + 32; if (iend > NKEEP) iend = NKEEP;
    int j = jw * 32 + lane;
    bool jv = (j < NKEEP);
    float jx1 = 0, jy1 = 0, jx2 = 0, jy2 = 0, ja = 0;
    if (jv) {
        float4 b = sbox[j];
        jx1 = b.x; jy1 = b.y; jx2 = b.z; jy2 = b.w;
        ja = sarea[j];
    }
    for (int i = i0; i < iend; i++) {
        float4 bi = sbox[i];
        float ai  = sarea[i];
        float iw = fminf(bi.z, jx2) - fmaxf(bi.x, jx1); iw = fmaxf(iw, 0.0f);
        float ih = fminf(bi.w, jy2) - fmaxf(bi.y, jy1); ih = fmaxf(ih, 0.0f);
        float inter = iw * ih;
        float uni   = ai + ja - inter;
        bool pred = jv && (inter / fmaxf(uni, 1e-8f) > 0.5f);
        unsigned m = __ballot_sync(0xFFFFFFFFu, pred);
        if (lane == 0) g_sup[i * 32 + jw] = m;
    }
}

// ---------------- stage 5: tile-blocked sequential NMS + output ----------------
__global__ void __launch_bounds__(256) k_scan(float* __restrict__ out) {
    extern __shared__ unsigned ssup[];   // 1024 x 33 words padded
    __shared__ unsigned svalid[32];
    __shared__ unsigned skeep[32];
    int t = threadIdx.x;

    for (int idx = t; idx < 32768; idx += 256) {
        int r = idx >> 5, w = idx & 31;
        ssup[r * SCAN_STRIDE + w] = (r < NKEEP) ? g_sup[idx] : 0u;
    }
    for (int base = 0; base < 1024; base += 256) {
        int i = base + t;
        float sc = (i < NKEEP) ? g_cscore[i] : 0.0f;
        unsigned bm = __ballot_sync(0xFFFFFFFFu, sc > 0.5f);
        if ((t & 31) == 0) svalid[i >> 5] = bm;
    }
    __syncthreads();

    if (t < 32) {
        int lane = t;
        unsigned rem = 0;
        unsigned keepw = 0;
        unsigned validw = svalid[lane];
        for (int tt = 0; tt < 32; tt++) {
            unsigned rowv[32];
#pragma unroll
            for (int b = 0; b < 32; b++)
                rowv[b] = ssup[(32 * tt + b) * SCAN_STRIDE + tt];
            unsigned W = __ballot_sync(0xFFFFFFFFu, (rem >> tt) & 1u);
            unsigned V = __shfl_sync(0xFFFFFFFFu, validw, tt);
            unsigned K = 0;
#pragma unroll
            for (int b = 0; b < 32; b++) {
                if (((V >> b) & 1u) && !((W >> b) & 1u) && ((rowv[b] & K) == 0u))
                    K |= 1u << b;
            }
            if (lane == tt) keepw = K;
#pragma unroll
            for (int s = 1; s < 32; s++) {
                if (s > tt) {
                    unsigned c = ssup[(32 * s + lane) * SCAN_STRIDE + tt];
                    if (c & K) rem |= 1u << s;
                }
            }
        }
        skeep[lane] = keepw;
    }
    __syncthreads();

    for (int base = 0; base < NKEEP; base += 256) {
        int i = base + t;
        if (i < NKEEP) {
            bool kp = (skeep[i >> 5] >> (i & 31)) & 1u;
            out[i]         = kp ? g_cscore[i] : 0.0f;
            out[NKEEP + i] = kp ? (float)g_ccls[i] : -1.0f;
            float4 b = kp ? g_box[i] : make_float4(0, 0, 0, 0);
            ((float4*)(out + 2 * NKEEP))[i] = b;
        }
    }
}

// ---------------- launch ----------------
extern "C" void kernel_launch(void* const* d_in, const int* in_sizes, int n_in,
                              void* d_out, int out_size) {
    const float*  cla     = (const float*)d_in[0];
    const float4* reg     = (const float4*)d_in[1];
    const float4* anchors = (const float4*)d_in[2];
    int A = in_sizes[0] / 80;
    float* out = (float*)d_out;

    cudaFuncSetAttribute(k_scan, cudaFuncAttributeMaxDynamicSharedMemorySize, SCAN_SMEM);

    k_reduce<<<1184, 256>>>(cla, A);
    k_compact<<<592, 256>>>(A / 4);
    k_rank<<<128, 256>>>(anchors, reg, cla);
    k_iou<<<129, 256>>>();
    k_scan<<<1, 256, SCAN_SMEM>>>(out);
}